// round 7
// baseline (speedup 1.0000x reference)
#include <cuda_runtime.h>
#include <math.h>

#define T_LEN   2000000
#define NTAGS   5
#define START_T 3
#define STOP_T  4

#define CHUNK   8
#define BLOCK1  256
#define LANES_ACT ((T_LEN - 1 + CHUNK - 1) / CHUNK)   // 250000
#define L_LAST    (LANES_ACT - 1)
#define NBLK      ((LANES_ACT + BLOCK1 - 1) / BLOCK1) // 977
#define PAD       (NBLK * BLOCK1)                     // 250112
#define TB_ROWS   (BLOCK1 * CHUNK)                    // 2048 rows per stage1 block
#define SSTR      (CHUNK + 1)                         // 9: odd stride, conflict-free

#define LN2_D   0.6931471805599453

// Phase-major staging for emulate: F_c[s*PAD + g]
__device__ float g_F0[CHUNK * PAD];
__device__ float g_F1[CHUNK * PAD];
__device__ float g_F2[CHUNK * PAD];

__device__ float  g_Pinc[9 * PAD];    // block-local inclusive matrix prefix (SoA)
__device__ int    g_pbinc[PAD];
__device__ float  g_goldB[NBLK];
__device__ float  g_Mblk[NBLK][9];
__device__ int    g_Bblk[NBLK];
__device__ float  g_Ebf[NBLK][9];     // block-exclusive prefix (fp32 + base)
__device__ int    g_EbB[NBLK];
__device__ float  g_u0f[3];
__device__ double g_c0d;
__device__ double g_partB[NBLK];
__device__ float  g_stop3[3];

__device__ __forceinline__ void renorm9(float* P, int& base) {
    float m = fmaxf(fmaxf(fmaxf(P[0], P[1]), fmaxf(P[2], P[3])),
                    fmaxf(fmaxf(P[4], P[5]), fmaxf(P[6], fmaxf(P[7], P[8]))));
    int e = (int)(__float_as_uint(m) >> 23) - 127;
    float sc = __uint_as_float((unsigned)(127 - e) << 23);
#pragma unroll
    for (int i = 0; i < 9; ++i) P[i] *= sc;
    base += e;
}

__device__ __forceinline__ void mm9(const float* Bm, const float* A, float* C) {
#pragma unroll
    for (int i = 0; i < 3; ++i)
#pragma unroll
        for (int j = 0; j < 3; ++j)
            C[i*3+j] = Bm[i*3+0]*A[0+j] + Bm[i*3+1]*A[3+j] + Bm[i*3+2]*A[6+j];
}

// Boundary vector: log((Pm x Eb).u0) + (bP+bE)*ln2 + c0 — fp32 core, 1 DADD per comp
__device__ __forceinline__ void boundaryA(const float* Pm, int bP,
                                          const float* Eb, int bE,
                                          const float* u0, double c0d,
                                          float* out3) {
    float Cd[9];
    mm9(Pm, Eb, Cd);
    double t = (double)(bP + bE) * LN2_D + c0d;
#pragma unroll
    for (int i = 0; i < 3; ++i) {
        float w = Cd[i*3+0]*u0[0] + Cd[i*3+1]*u0[1] + Cd[i*3+2]*u0[2];
        out3[i] = (float)((double)__logf(w) + t);
    }
}

// ========== K1: fused transpose + chunk matrices + gold + in-block scan ==========
__global__ void __launch_bounds__(BLOCK1) k_stage1(
        const float* __restrict__ feats, const int* __restrict__ tags,
        const float* __restrict__ trans) {
    __shared__ float sF0[BLOCK1 * SSTR];
    __shared__ float sF1[BLOCK1 * SSTR];
    __shared__ float sF2[BLOCK1 * SSTR];
    __shared__ int   sT [BLOCK1 * SSTR];
    __shared__ float sP[BLOCK1][9];
    __shared__ int   sB[BLOCK1];
    __shared__ float sG[BLOCK1];
    __shared__ float sTr[25];

    const float L2E = 1.4426950408889634f;
    int tid = threadIdx.x;
    int B0  = blockIdx.x * BLOCK1;
    int tbase = 1 + B0 * CHUNK;

    if (tid < 25) sTr[tid] = trans[tid];
    float Tl[9];
#pragma unroll
    for (int i = 0; i < 3; ++i)
#pragma unroll
        for (int k = 0; k < 3; ++k)
            Tl[i * 3 + k] = exp2f(L2E * __ldg(&trans[i * NTAGS + k]));

    // coalesced read of feats rows -> smem (transposed layout, stride 9)
    for (int idx = tid; idx < TB_ROWS * 5; idx += BLOCK1) {
        int tl = idx / 5, c = idx - 5 * tl;
        int t = tbase + tl;
        if (c < 3 && t < T_LEN) {
            float v = feats[t * 5 + c];
            int si = (tl >> 3) * SSTR + (tl & 7);
            if (c == 0) sF0[si] = v;
            else if (c == 1) sF1[si] = v;
            else sF2[si] = v;
        }
    }
    for (int tl = tid; tl < TB_ROWS; tl += BLOCK1) {
        int t = tbase + tl;
        if (t < T_LEN) sT[(tl >> 3) * SSTR + (tl & 7)] = tags[t];
    }
    __syncthreads();

    // write phase-major arrays for emulate (coalesced, conflict-free smem reads)
#pragma unroll
    for (int k = 0; k < CHUNK; ++k) {
        int si = tid * SSTR + k;
        int oo = k * PAD + (B0 + tid);
        g_F0[oo] = sF0[si];
        g_F1[oo] = sF1[si];
        g_F2[oo] = sF2[si];
    }

    int g     = B0 + tid;
    int start = 1 + g * CHUNK;
    int n     = (g < LANES_ACT) ? min(CHUNK, T_LEN - start) : 0;

    float P[9] = {1.f, 0.f, 0.f, 0.f, 1.f, 0.f, 0.f, 0.f, 1.f};
    int   base = 0;
    float gold = 0.f;

    if (n > 0) {
        int prev = (tid == 0) ? __ldg(&tags[B0 * CHUNK]) : sT[tid * SSTR - SSTR + 7];
        int sbase = tid * SSTR;
#pragma unroll
        for (int s = 0; s < CHUNK; ++s) {
            if (s < n) {
                float f0 = sF0[sbase + s], f1 = sF1[sbase + s], f2 = sF2[sbase + s];
                int cur = sT[sbase + s];
                float e0 = exp2f(L2E * f0), e1 = exp2f(L2E * f1), e2 = exp2f(L2E * f2);
                float a0 = e0 * Tl[0], a1 = e0 * Tl[1], a2 = e0 * Tl[2];
                float b0 = e1 * Tl[3], b1 = e1 * Tl[4], b2 = e1 * Tl[5];
                float d0 = e2 * Tl[6], d1 = e2 * Tl[7], d2 = e2 * Tl[8];
                float q0 = a0*P[0] + a1*P[3] + a2*P[6];
                float q1 = a0*P[1] + a1*P[4] + a2*P[7];
                float q2 = a0*P[2] + a1*P[5] + a2*P[8];
                float q3 = b0*P[0] + b1*P[3] + b2*P[6];
                float q4 = b0*P[1] + b1*P[4] + b2*P[7];
                float q5 = b0*P[2] + b1*P[5] + b2*P[8];
                float q6 = d0*P[0] + d1*P[3] + d2*P[6];
                float q7 = d0*P[1] + d1*P[4] + d2*P[7];
                float q8 = d0*P[2] + d1*P[5] + d2*P[8];
                P[0]=q0;P[1]=q1;P[2]=q2;P[3]=q3;P[4]=q4;P[5]=q5;P[6]=q6;P[7]=q7;P[8]=q8;
                float emit = (cur == 0) ? f0 : ((cur == 1) ? f1 : f2);
                gold += emit + sTr[cur * NTAGS + prev];
                prev = cur;
            }
        }
        renorm9(P, base);
    }

    // per-block gold (ordered tree)
    sG[tid] = gold;
    __syncthreads();
    for (int k = BLOCK1 / 2; k > 0; k >>= 1) {
        if (tid < k) sG[tid] += sG[tid + k];
        __syncthreads();
    }
    if (tid == 0) g_goldB[blockIdx.x] = sG[0];

    // Hillis-Steele inclusive scan of lane matrices (later on left)
#pragma unroll
    for (int i = 0; i < 9; ++i) sP[tid][i] = P[i];
    sB[tid] = base;
    __syncthreads();
    for (int s = 1; s < BLOCK1; s <<= 1) {
        float A[9], C[9]; int nb = 0; bool act = (tid >= s);
        if (act) {
            float Bm[9];
#pragma unroll
            for (int i = 0; i < 9; ++i) { Bm[i] = sP[tid][i]; A[i] = sP[tid - s][i]; }
            nb = sB[tid] + sB[tid - s];
            mm9(Bm, A, C);
            renorm9(C, nb);
        }
        __syncthreads();
        if (act) {
#pragma unroll
            for (int i = 0; i < 9; ++i) sP[tid][i] = C[i];
            sB[tid] = nb;
        }
        __syncthreads();
    }

#pragma unroll
    for (int i = 0; i < 9; ++i) g_Pinc[i * PAD + g] = sP[tid][i];
    g_pbinc[g] = sB[tid];
    if (tid == BLOCK1 - 1) {
#pragma unroll
        for (int i = 0; i < 9; ++i) g_Mblk[blockIdx.x][i] = sP[tid][i];
        g_Bblk[blockIdx.x] = sB[tid];
    }
}

// ========== K2: exclusive prefix over NBLK block totals (fp32+base) ==========
#define K2_ITEMS 4                       // 256*4 = 1024 >= NBLK
__global__ void __launch_bounds__(BLOCK1) k_blockscan(
        const float* __restrict__ feats, const float* __restrict__ trans) {
    __shared__ float sM[BLOCK1][9];
    __shared__ int   sb[BLOCK1];
    int tid = threadIdx.x;

    float loc[K2_ITEMS][9]; int lb[K2_ITEMS];
    float tot[9] = {1.f,0.f,0.f, 0.f,1.f,0.f, 0.f,0.f,1.f};
    int   bt = 0;
#pragma unroll
    for (int k = 0; k < K2_ITEMS; ++k) {
        int i = tid * K2_ITEMS + k;
        if (i < NBLK) {
#pragma unroll
            for (int j = 0; j < 9; ++j) loc[k][j] = g_Mblk[i][j];
            lb[k] = g_Bblk[i];
            float C[9];
            mm9(loc[k], tot, C);
            bt += lb[k];
            renorm9(C, bt);
#pragma unroll
            for (int j = 0; j < 9; ++j) tot[j] = C[j];
        } else {
#pragma unroll
            for (int j = 0; j < 9; ++j) loc[k][j] = (j % 4 == 0) ? 1.f : 0.f;
            lb[k] = 0;
        }
    }
#pragma unroll
    for (int j = 0; j < 9; ++j) sM[tid][j] = tot[j];
    sb[tid] = bt;
    __syncthreads();

    for (int s = 1; s < BLOCK1; s <<= 1) {
        float A[9], C[9]; int nb = 0; bool act = (tid >= s);
        if (act) {
            float Bm[9];
#pragma unroll
            for (int j = 0; j < 9; ++j) { Bm[j] = sM[tid][j]; A[j] = sM[tid - s][j]; }
            nb = sb[tid] + sb[tid - s];
            mm9(Bm, A, C);
            renorm9(C, nb);
        }
        __syncthreads();
        if (act) {
#pragma unroll
            for (int j = 0; j < 9; ++j) sM[tid][j] = C[j];
            sb[tid] = nb;
        }
        __syncthreads();
    }

    float E[9]; int be;
    if (tid == 0) {
#pragma unroll
        for (int j = 0; j < 9; ++j) E[j] = (j % 4 == 0) ? 1.f : 0.f;
        be = 0;
    } else {
#pragma unroll
        for (int j = 0; j < 9; ++j) E[j] = sM[tid - 1][j];
        be = sb[tid - 1];
    }
#pragma unroll
    for (int k = 0; k < K2_ITEMS; ++k) {
        int i = tid * K2_ITEMS + k;
        if (i < NBLK) {
#pragma unroll
            for (int j = 0; j < 9; ++j) g_Ebf[i][j] = E[j];
            g_EbB[i] = be;
            float C[9];
            mm9(loc[k], E, C);
            be += lb[k];
            renorm9(C, be);
#pragma unroll
            for (int j = 0; j < 9; ++j) E[j] = C[j];
        }
    }

    if (tid == 0) {
        double v0[3];
        for (int i = 0; i < 3; ++i) {
            double a[5]; double m = -1e300;
            for (int j = 0; j < 5; ++j) {
                a[j] = (double)trans[i * NTAGS + j] + ((j == START_T) ? 0.0 : -10000.0);
                if (a[j] > m) m = a[j];
            }
            double ss = 0.0;
            for (int j = 0; j < 5; ++j) ss += exp(a[j] - m);
            v0[i] = m + log(ss) + (double)feats[i];
        }
        double c0 = fmax(fmax(v0[0], v0[1]), v0[2]);
        g_c0d = c0;
        for (int j = 0; j < 3; ++j) g_u0f[j] = (float)exp(v0[j] - c0);
    }
}

// ========== K3: boundary vectors + fp32 absolute-scale emulation ==========
__global__ void __launch_bounds__(BLOCK1) k_emulate(const float* __restrict__ trans) {
    __shared__ float  sTr[25];
    __shared__ double sPart[BLOCK1];
    int tid = threadIdx.x;
    if (tid < 25) sTr[tid] = trans[tid];
    __syncthreads();

    int g = blockIdx.x * BLOCK1 + tid;
    double part = 0.0;

    if (g < LANES_ACT) {
        int b = blockIdx.x;
        float Eb[9]; int bE = g_EbB[b];
#pragma unroll
        for (int i = 0; i < 9; ++i) Eb[i] = g_Ebf[b][i];
        float u0[3] = {g_u0f[0], g_u0f[1], g_u0f[2]};
        double c0d = g_c0d;

        float ex[9]; int bL;
        if (tid == 0) {
#pragma unroll
            for (int i = 0; i < 9; ++i) ex[i] = (i % 4 == 0) ? 1.f : 0.f;
            bL = 0;
        } else {
#pragma unroll
            for (int i = 0; i < 9; ++i) ex[i] = g_Pinc[i * PAD + (g - 1)];
            bL = g_pbinc[g - 1];
        }
        float A[3];
        boundaryA(ex, bL, Eb, bE, u0, c0d, A);

        float in9[9];
#pragma unroll
        for (int i = 0; i < 9; ++i) in9[i] = g_Pinc[i * PAD + g];
        int bI = g_pbinc[g];
        float Bn[3];
        boundaryA(in9, bI, Eb, bE, u0, c0d, Bn);

        float fv0 = A[0], fv1 = A[1], fv2 = A[2];
        int n = min(CHUNK, T_LEN - (1 + g * CHUNK));

        float t00 = sTr[0],  t01 = sTr[1],  t02 = sTr[2];
        float t10 = sTr[5],  t11 = sTr[6],  t12 = sTr[7];
        float t20 = sTr[10], t21 = sTr[11], t22 = sTr[12];

        const float* p0 = g_F0 + g;
        const float* p1 = g_F1 + g;
        const float* p2 = g_F2 + g;

#pragma unroll
        for (int s = 0; s < CHUNK; ++s) {
            if (s < n) {
                float f0 = __ldg(p0 + s * PAD);
                float f1 = __ldg(p1 + s * PAD);
                float f2 = __ldg(p2 + s * PAD);
                float a00=__fadd_rn(fv0,t00), a01=__fadd_rn(fv1,t01), a02=__fadd_rn(fv2,t02);
                float a10=__fadd_rn(fv0,t10), a11=__fadd_rn(fv1,t11), a12=__fadd_rn(fv2,t12);
                float a20=__fadd_rn(fv0,t20), a21=__fadd_rn(fv1,t21), a22=__fadd_rn(fv2,t22);
                float m0=fmaxf(fmaxf(a00,a01),a02);
                float m1=fmaxf(fmaxf(a10,a11),a12);
                float m2=fmaxf(fmaxf(a20,a21),a22);
                float s0=__expf(a00-m0)+__expf(a01-m0)+__expf(a02-m0);
                float s1=__expf(a10-m1)+__expf(a11-m1)+__expf(a12-m1);
                float s2=__expf(a20-m2)+__expf(a21-m2)+__expf(a22-m2);
                fv0=__fadd_rn(__fadd_rn(__logf(s0),m0),f0);
                fv1=__fadd_rn(__fadd_rn(__logf(s1),m1),f1);
                fv2=__fadd_rn(__fadd_rn(__logf(s2),m2),f2);
            }
        }

        if (g < L_LAST) {
            part = (((double)fv0 - (double)Bn[0])
                  + ((double)fv1 - (double)Bn[1])
                  + ((double)fv2 - (double)Bn[2])) / 3.0;
        } else {
            g_stop3[0] = __fadd_rn(fv0, sTr[STOP_T * NTAGS + 0]);
            g_stop3[1] = __fadd_rn(fv1, sTr[STOP_T * NTAGS + 1]);
            g_stop3[2] = __fadd_rn(fv2, sTr[STOP_T * NTAGS + 2]);
            part = 0.0;
        }
    }

    sPart[tid] = part;
    __syncthreads();
    for (int k = BLOCK1 / 2; k > 0; k >>= 1) {
        if (tid < k) sPart[tid] += sPart[tid + k];
        __syncthreads();
    }
    if (tid == 0) g_partB[blockIdx.x] = sPart[0];
}

// ========== K4: final reductions + epilogue ==========
__global__ void __launch_bounds__(512) crf_out(
        const float* __restrict__ feats, const int* __restrict__ tags,
        const float* __restrict__ trans, float* __restrict__ out) {
    __shared__ double red[512];
    int tid = threadIdx.x;

    double s = 0.0;
    for (int i = tid; i < NBLK; i += 512) s += g_partB[i];
    red[tid] = s; __syncthreads();
    for (int k = 256; k > 0; k >>= 1) {
        if (tid < k) red[tid] += red[tid + k];
        __syncthreads();
    }
    double mu = red[0]; __syncthreads();

    double sg = 0.0;
    for (int i = tid; i < NBLK; i += 512) sg += (double)g_goldB[i];
    red[tid] = sg; __syncthreads();
    for (int k = 256; k > 0; k >>= 1) {
        if (tid < k) red[tid] += red[tid + k];
        __syncthreads();
    }
    double goldsum = red[0];

    if (tid == 0) {
        double b0 = (double)g_stop3[0], b1 = (double)g_stop3[1], b2 = (double)g_stop3[2];
        double m = fmax(fmax(b0, b1), b2);
        double alpha = m + log(exp(b0 - m) + exp(b1 - m) + exp(b2 - m)) + mu;

        int tg0 = tags[0];
        int tgL = tags[T_LEN - 1];
        double gold = goldsum
                    + (double)trans[tg0 * NTAGS + START_T]
                    + (double)feats[tg0]
                    + (double)trans[STOP_T * NTAGS + tgL];
        out[0] = (float)(alpha - gold);
    }
}

extern "C" void kernel_launch(void* const* d_in, const int* in_sizes, int n_in,
                              void* d_out, int out_size) {
    const float* feats = nullptr;
    const int*   tags  = nullptr;
    const float* trans = nullptr;
    for (int i = 0; i < n_in; ++i) {
        if (in_sizes[i] == NTAGS * NTAGS)      trans = (const float*)d_in[i];
        else if (in_sizes[i] == T_LEN)         tags  = (const int*)d_in[i];
        else                                   feats = (const float*)d_in[i];
    }
    float* out = (float*)d_out;

    k_stage1<<<NBLK, BLOCK1>>>(feats, tags, trans);
    k_blockscan<<<1, BLOCK1>>>(feats, trans);
    k_emulate<<<NBLK, BLOCK1>>>(trans);
    crf_out<<<1, 512>>>(feats, tags, trans, out);
}

// round 8
// speedup vs baseline: 1.0798x; 1.0798x over previous
#include <cuda_runtime.h>
#include <math.h>

#define T_LEN   2000000
#define NTAGS   5
#define START_T 3
#define STOP_T  4

#define CHUNK   8
#define BLOCK1  256
#define LANES_ACT ((T_LEN - 1 + CHUNK - 1) / CHUNK)   // 250000
#define L_LAST    (LANES_ACT - 1)
#define NBLK      ((LANES_ACT + BLOCK1 - 1) / BLOCK1) // 977
#define PAD       (NBLK * BLOCK1)                     // 250112
#define SSTR      (CHUNK + 1)                         // 9

#define TB_CH   128
#define TB_ROWS (TB_CH * CHUNK)                       // 1024
#define NT_BLK  ((LANES_ACT + TB_CH - 1) / TB_CH)     // 1954

#define K2_ITEMS 4                                    // 256*4 >= NBLK

#define LN2_D   0.6931471805599453

// Phase-major staging: F_c[s*PAD + g], Tg[s*PAD + g]
__device__ float g_F0[CHUNK * PAD];
__device__ float g_F1[CHUNK * PAD];
__device__ float g_F2[CHUNK * PAD];
__device__ int   g_Tg[CHUNK * PAD];

__device__ float  g_Pinc[9 * PAD];    // block-local inclusive matrix prefix (SoA)
__device__ int    g_pbinc[PAD];
__device__ float  g_goldB[NBLK];
__device__ float  g_Mblk[NBLK][9];
__device__ int    g_Bblk[NBLK];
__device__ float  g_Ebf[NBLK][9];     // block-exclusive prefix (fp32 + base)
__device__ int    g_EbB[NBLK];
__device__ float  g_u0f[3];
__device__ double g_c0d;
__device__ double g_partB[NBLK];
__device__ float  g_stop3[3];
__device__ unsigned g_tick1;
__device__ unsigned g_tick2;

__device__ __forceinline__ void renorm9(float* P, int& base) {
    float m = fmaxf(fmaxf(fmaxf(P[0], P[1]), fmaxf(P[2], P[3])),
                    fmaxf(fmaxf(P[4], P[5]), fmaxf(P[6], fmaxf(P[7], P[8]))));
    int e = (int)(__float_as_uint(m) >> 23) - 127;
    float sc = __uint_as_float((unsigned)(127 - e) << 23);
#pragma unroll
    for (int i = 0; i < 9; ++i) P[i] *= sc;
    base += e;
}

__device__ __forceinline__ void mm9(const float* Bm, const float* A, float* C) {
#pragma unroll
    for (int i = 0; i < 3; ++i)
#pragma unroll
        for (int j = 0; j < 3; ++j)
            C[i*3+j] = Bm[i*3+0]*A[0+j] + Bm[i*3+1]*A[3+j] + Bm[i*3+2]*A[6+j];
}

__device__ __forceinline__ void boundaryA(const float* Pm, int bP,
                                          const float* Eb, int bE,
                                          const float* u0, double c0d,
                                          float* out3) {
    float Cd[9];
    mm9(Pm, Eb, Cd);
    double t = (double)(bP + bE) * LN2_D + c0d;
#pragma unroll
    for (int i = 0; i < 3; ++i) {
        float w = Cd[i*3+0]*u0[0] + Cd[i*3+1]*u0[1] + Cd[i*3+2]*u0[2];
        out3[i] = (float)((double)__logf(w) + t);
    }
}

// ========== K0: phase-major transpose ==========
__global__ void __launch_bounds__(256) k_transpose(
        const float* __restrict__ feats, const int* __restrict__ tags) {
    __shared__ float sF[3][TB_CH * SSTR];
    __shared__ int   sT [TB_CH * SSTR];
    int tid = threadIdx.x;
    int tbase = 1 + blockIdx.x * TB_ROWS;
    int Gbase = blockIdx.x * TB_CH;

    for (int idx = tid; idx < TB_ROWS * 5; idx += 256) {
        int tl = idx / 5, c = idx - 5 * tl;
        int t = tbase + tl;
        if (c < 3 && t < T_LEN)
            sF[c][(tl >> 3) * SSTR + (tl & 7)] = feats[t * 5 + c];
    }
    for (int tl = tid; tl < TB_ROWS; tl += 256) {
        int t = tbase + tl;
        if (t < T_LEN) sT[(tl >> 3) * SSTR + (tl & 7)] = tags[t];
    }
    __syncthreads();

    for (int o = tid; o < CHUNK * TB_CH; o += 256) {
        int s = o / TB_CH, lg = o - TB_CH * s;
        int si = lg * SSTR + s;
        int oo = s * PAD + (Gbase + lg);
        g_F0[oo] = sF[0][si];
        g_F1[oo] = sF[1][si];
        g_F2[oo] = sF[2][si];
        g_Tg[oo] = sT[si];
    }
}

// ========== K1: chunk matrices + gold + in-block scan (+ folded block scan) ========
__global__ void __launch_bounds__(BLOCK1) k_chunks(
        const float* __restrict__ feats, const int* __restrict__ tags,
        const float* __restrict__ trans) {
    __shared__ float sP[BLOCK1][9];
    __shared__ int   sB[BLOCK1];
    __shared__ float sG[BLOCK1];
    __shared__ float sTr[25];
    __shared__ bool  sLast;

    const float L2E = 1.4426950408889634f;
    int tid = threadIdx.x;
    if (tid < 25) sTr[tid] = trans[tid];

    float Tl[9];
#pragma unroll
    for (int i = 0; i < 3; ++i)
#pragma unroll
        for (int k = 0; k < 3; ++k)
            Tl[i * 3 + k] = exp2f(L2E * __ldg(&trans[i * NTAGS + k]));
    __syncthreads();

    int g     = blockIdx.x * BLOCK1 + tid;
    int start = 1 + g * CHUNK;
    int n     = (g < LANES_ACT) ? min(CHUNK, T_LEN - start) : 0;

    float P[9] = {1.f, 0.f, 0.f, 0.f, 1.f, 0.f, 0.f, 0.f, 1.f};
    int   base = 0;
    float gold = 0.f;

#define K1STEP() do {                                                        \
        float f0 = __ldg(p0), f1 = __ldg(p1), f2 = __ldg(p2);                \
        int cur = __ldg(pt);                                                 \
        p0 += PAD; p1 += PAD; p2 += PAD; pt += PAD;                          \
        float e0 = exp2f(L2E * f0), e1 = exp2f(L2E * f1), e2 = exp2f(L2E * f2);\
        float a0 = e0 * Tl[0], a1 = e0 * Tl[1], a2 = e0 * Tl[2];             \
        float b0 = e1 * Tl[3], b1 = e1 * Tl[4], b2 = e1 * Tl[5];             \
        float d0 = e2 * Tl[6], d1 = e2 * Tl[7], d2 = e2 * Tl[8];             \
        float q0 = a0*P[0] + a1*P[3] + a2*P[6];                              \
        float q1 = a0*P[1] + a1*P[4] + a2*P[7];                              \
        float q2 = a0*P[2] + a1*P[5] + a2*P[8];                              \
        float q3 = b0*P[0] + b1*P[3] + b2*P[6];                              \
        float q4 = b0*P[1] + b1*P[4] + b2*P[7];                              \
        float q5 = b0*P[2] + b1*P[5] + b2*P[8];                              \
        float q6 = d0*P[0] + d1*P[3] + d2*P[6];                              \
        float q7 = d0*P[1] + d1*P[4] + d2*P[7];                              \
        float q8 = d0*P[2] + d1*P[5] + d2*P[8];                              \
        P[0]=q0;P[1]=q1;P[2]=q2;P[3]=q3;P[4]=q4;P[5]=q5;P[6]=q6;P[7]=q7;P[8]=q8;\
        float emit = (cur == 0) ? f0 : ((cur == 1) ? f1 : f2);               \
        gold += emit + sTr[cur * NTAGS + prev];                              \
        prev = cur;                                                          \
    } while (0)

    if (n > 0) {
        int prev = __ldg(&tags[start - 1]);
        const float* p0 = g_F0 + g;
        const float* p1 = g_F1 + g;
        const float* p2 = g_F2 + g;
        const int*   pt = g_Tg + g;
        if (n == CHUNK) {
#pragma unroll
            for (int s = 0; s < CHUNK; ++s) K1STEP();
        } else {
            for (int s = 0; s < n; ++s) K1STEP();
        }
        renorm9(P, base);
    }
#undef K1STEP

    // per-block gold (ordered tree)
    sG[tid] = gold;
    __syncthreads();
    for (int k = BLOCK1 / 2; k > 0; k >>= 1) {
        if (tid < k) sG[tid] += sG[tid + k];
        __syncthreads();
    }
    if (tid == 0) g_goldB[blockIdx.x] = sG[0];

    // Hillis-Steele inclusive scan of lane matrices (later on left)
#pragma unroll
    for (int i = 0; i < 9; ++i) sP[tid][i] = P[i];
    sB[tid] = base;
    __syncthreads();
    for (int s = 1; s < BLOCK1; s <<= 1) {
        float A[9], C[9]; int nb = 0; bool act = (tid >= s);
        if (act) {
            float Bm[9];
#pragma unroll
            for (int i = 0; i < 9; ++i) { Bm[i] = sP[tid][i]; A[i] = sP[tid - s][i]; }
            nb = sB[tid] + sB[tid - s];
            mm9(Bm, A, C);
            renorm9(C, nb);
        }
        __syncthreads();
        if (act) {
#pragma unroll
            for (int i = 0; i < 9; ++i) sP[tid][i] = C[i];
            sB[tid] = nb;
        }
        __syncthreads();
    }

#pragma unroll
    for (int i = 0; i < 9; ++i) g_Pinc[i * PAD + g] = sP[tid][i];
    g_pbinc[g] = sB[tid];
    if (tid == BLOCK1 - 1) {
#pragma unroll
        for (int i = 0; i < 9; ++i) g_Mblk[blockIdx.x][i] = sP[tid][i];
        g_Bblk[blockIdx.x] = sB[tid];
    }

    // -------- last-block ticket: fold the block-exclusive scan --------
    if (tid == 0) {
        __threadfence();
        unsigned v = atomicAdd(&g_tick1, 1u);
        sLast = (v == (unsigned)(NBLK - 1));
    }
    __syncthreads();
    if (!sLast) return;

    // phase 1: per-thread serial product of items [4t, 4t+4)
    {
        float tot[9] = {1.f,0.f,0.f, 0.f,1.f,0.f, 0.f,0.f,1.f};
        int bt = 0;
#pragma unroll
        for (int k = 0; k < K2_ITEMS; ++k) {
            int i = tid * K2_ITEMS + k;
            if (i < NBLK) {
                float M[9], C[9];
#pragma unroll
                for (int j = 0; j < 9; ++j) M[j] = g_Mblk[i][j];
                mm9(M, tot, C);
                bt += g_Bblk[i];
                renorm9(C, bt);
#pragma unroll
                for (int j = 0; j < 9; ++j) tot[j] = C[j];
            }
        }
#pragma unroll
        for (int j = 0; j < 9; ++j) sP[tid][j] = tot[j];
        sB[tid] = bt;
    }
    __syncthreads();

    for (int s = 1; s < BLOCK1; s <<= 1) {
        float A[9], C[9]; int nb = 0; bool act = (tid >= s);
        if (act) {
            float Bm[9];
#pragma unroll
            for (int j = 0; j < 9; ++j) { Bm[j] = sP[tid][j]; A[j] = sP[tid - s][j]; }
            nb = sB[tid] + sB[tid - s];
            mm9(Bm, A, C);
            renorm9(C, nb);
        }
        __syncthreads();
        if (act) {
#pragma unroll
            for (int j = 0; j < 9; ++j) sP[tid][j] = C[j];
            sB[tid] = nb;
        }
        __syncthreads();
    }

    // phase 2: emit per-block exclusive prefixes
    {
        float E[9]; int be;
        if (tid == 0) {
#pragma unroll
            for (int j = 0; j < 9; ++j) E[j] = (j % 4 == 0) ? 1.f : 0.f;
            be = 0;
        } else {
#pragma unroll
            for (int j = 0; j < 9; ++j) E[j] = sP[tid - 1][j];
            be = sB[tid - 1];
        }
#pragma unroll
        for (int k = 0; k < K2_ITEMS; ++k) {
            int i = tid * K2_ITEMS + k;
            if (i < NBLK) {
#pragma unroll
                for (int j = 0; j < 9; ++j) g_Ebf[i][j] = E[j];
                g_EbB[i] = be;
                float M[9], C[9];
#pragma unroll
                for (int j = 0; j < 9; ++j) M[j] = g_Mblk[i][j];
                mm9(M, E, C);
                be += g_Bblk[i];
                renorm9(C, be);
#pragma unroll
                for (int j = 0; j < 9; ++j) E[j] = C[j];
            }
        }
    }

    if (tid == 0) {
        double v0[3];
        for (int i = 0; i < 3; ++i) {
            double a[5]; double m = -1e300;
            for (int j = 0; j < 5; ++j) {
                a[j] = (double)trans[i * NTAGS + j] + ((j == START_T) ? 0.0 : -10000.0);
                if (a[j] > m) m = a[j];
            }
            double ss = 0.0;
            for (int j = 0; j < 5; ++j) ss += exp(a[j] - m);
            v0[i] = m + log(ss) + (double)feats[i];
        }
        double c0 = fmax(fmax(v0[0], v0[1]), v0[2]);
        g_c0d = c0;
        for (int j = 0; j < 3; ++j) g_u0f[j] = (float)exp(v0[j] - c0);
        g_tick1 = 0;                      // reset for graph replay
    }
}

// ========== K3: boundary vectors + emulation (+ folded final reduction) ==========
__global__ void __launch_bounds__(BLOCK1) k_emulate(
        const float* __restrict__ feats, const int* __restrict__ tags,
        const float* __restrict__ trans, float* __restrict__ out) {
    __shared__ float  sTr[25];
    __shared__ double sPart[BLOCK1];
    __shared__ bool   sLast;
    int tid = threadIdx.x;
    if (tid < 25) sTr[tid] = trans[tid];
    __syncthreads();

    int g = blockIdx.x * BLOCK1 + tid;
    double part = 0.0;

    if (g < LANES_ACT) {
        int b = blockIdx.x;
        float Eb[9]; int bE = g_EbB[b];
#pragma unroll
        for (int i = 0; i < 9; ++i) Eb[i] = g_Ebf[b][i];
        float u0[3] = {g_u0f[0], g_u0f[1], g_u0f[2]};
        double c0d = g_c0d;

        float ex[9]; int bL;
        if (tid == 0) {
#pragma unroll
            for (int i = 0; i < 9; ++i) ex[i] = (i % 4 == 0) ? 1.f : 0.f;
            bL = 0;
        } else {
#pragma unroll
            for (int i = 0; i < 9; ++i) ex[i] = g_Pinc[i * PAD + (g - 1)];
            bL = g_pbinc[g - 1];
        }
        float A[3];
        boundaryA(ex, bL, Eb, bE, u0, c0d, A);

        float in9[9];
#pragma unroll
        for (int i = 0; i < 9; ++i) in9[i] = g_Pinc[i * PAD + g];
        int bI = g_pbinc[g];
        float Bn[3];
        boundaryA(in9, bI, Eb, bE, u0, c0d, Bn);

        float fv0 = A[0], fv1 = A[1], fv2 = A[2];
        int n = min(CHUNK, T_LEN - (1 + g * CHUNK));

        float t00 = sTr[0],  t01 = sTr[1],  t02 = sTr[2];
        float t10 = sTr[5],  t11 = sTr[6],  t12 = sTr[7];
        float t20 = sTr[10], t21 = sTr[11], t22 = sTr[12];

        const float* p0 = g_F0 + g;
        const float* p1 = g_F1 + g;
        const float* p2 = g_F2 + g;

#define EMSTEP() do {                                                        \
        float f0 = __ldg(p0), f1 = __ldg(p1), f2 = __ldg(p2);                \
        p0 += PAD; p1 += PAD; p2 += PAD;                                     \
        float a00=__fadd_rn(fv0,t00), a01=__fadd_rn(fv1,t01), a02=__fadd_rn(fv2,t02);\
        float a10=__fadd_rn(fv0,t10), a11=__fadd_rn(fv1,t11), a12=__fadd_rn(fv2,t12);\
        float a20=__fadd_rn(fv0,t20), a21=__fadd_rn(fv1,t21), a22=__fadd_rn(fv2,t22);\
        float m0=fmaxf(fmaxf(a00,a01),a02);                                  \
        float m1=fmaxf(fmaxf(a10,a11),a12);                                  \
        float m2=fmaxf(fmaxf(a20,a21),a22);                                  \
        float s0=__expf(a00-m0)+__expf(a01-m0)+__expf(a02-m0);               \
        float s1=__expf(a10-m1)+__expf(a11-m1)+__expf(a12-m1);               \
        float s2=__expf(a20-m2)+__expf(a21-m2)+__expf(a22-m2);               \
        fv0=__fadd_rn(__fadd_rn(__logf(s0),m0),f0);                          \
        fv1=__fadd_rn(__fadd_rn(__logf(s1),m1),f1);                          \
        fv2=__fadd_rn(__fadd_rn(__logf(s2),m2),f2);                          \
    } while (0)

        if (n == CHUNK) {
#pragma unroll
            for (int s = 0; s < CHUNK; ++s) EMSTEP();
        } else {
            for (int s = 0; s < n; ++s) EMSTEP();
        }
#undef EMSTEP

        if (g < L_LAST) {
            part = (((double)fv0 - (double)Bn[0])
                  + ((double)fv1 - (double)Bn[1])
                  + ((double)fv2 - (double)Bn[2])) / 3.0;
        } else {
            g_stop3[0] = __fadd_rn(fv0, sTr[STOP_T * NTAGS + 0]);
            g_stop3[1] = __fadd_rn(fv1, sTr[STOP_T * NTAGS + 1]);
            g_stop3[2] = __fadd_rn(fv2, sTr[STOP_T * NTAGS + 2]);
            part = 0.0;
        }
    }

    sPart[tid] = part;
    __syncthreads();
    for (int k = BLOCK1 / 2; k > 0; k >>= 1) {
        if (tid < k) sPart[tid] += sPart[tid + k];
        __syncthreads();
    }
    if (tid == 0) g_partB[blockIdx.x] = sPart[0];

    // -------- last-block ticket: fold final reduction + epilogue --------
    if (tid == 0) {
        __threadfence();
        unsigned v = atomicAdd(&g_tick2, 1u);
        sLast = (v == (unsigned)(NBLK - 1));
    }
    __syncthreads();
    if (!sLast) return;

    double s = 0.0;
    for (int i = tid; i < NBLK; i += BLOCK1) s += g_partB[i];
    sPart[tid] = s; __syncthreads();
    for (int k = BLOCK1 / 2; k > 0; k >>= 1) {
        if (tid < k) sPart[tid] += sPart[tid + k];
        __syncthreads();
    }
    double mu = sPart[0]; __syncthreads();

    double sg = 0.0;
    for (int i = tid; i < NBLK; i += BLOCK1) sg += (double)g_goldB[i];
    sPart[tid] = sg; __syncthreads();
    for (int k = BLOCK1 / 2; k > 0; k >>= 1) {
        if (tid < k) sPart[tid] += sPart[tid + k];
        __syncthreads();
    }
    double goldsum = sPart[0];

    if (tid == 0) {
        double b0 = (double)g_stop3[0], b1 = (double)g_stop3[1], b2 = (double)g_stop3[2];
        double m = fmax(fmax(b0, b1), b2);
        double alpha = m + log(exp(b0 - m) + exp(b1 - m) + exp(b2 - m)) + mu;

        int tg0 = tags[0];
        int tgL = tags[T_LEN - 1];
        double gold = goldsum
                    + (double)trans[tg0 * NTAGS + START_T]
                    + (double)feats[tg0]
                    + (double)trans[STOP_T * NTAGS + tgL];
        out[0] = (float)(alpha - gold);
        g_tick2 = 0;                      // reset for graph replay
    }
}

extern "C" void kernel_launch(void* const* d_in, const int* in_sizes, int n_in,
                              void* d_out, int out_size) {
    const float* feats = nullptr;
    const int*   tags  = nullptr;
    const float* trans = nullptr;
    for (int i = 0; i < n_in; ++i) {
        if (in_sizes[i] == NTAGS * NTAGS)      trans = (const float*)d_in[i];
        else if (in_sizes[i] == T_LEN)         tags  = (const int*)d_in[i];
        else                                   feats = (const float*)d_in[i];
    }
    float* out = (float*)d_out;

    k_transpose<<<NT_BLK, 256>>>(feats, tags);
    k_chunks<<<NBLK, BLOCK1>>>(feats, tags, trans);
    k_emulate<<<NBLK, BLOCK1>>>(feats, tags, trans, out);
}

// round 9
// speedup vs baseline: 1.2835x; 1.1887x over previous
#include <cuda_runtime.h>
#include <math.h>

#define T_LEN   2000000
#define NTAGS   5
#define START_T 3
#define STOP_T  4

#define CHUNK   8
#define BLOCK1  256
#define LANES_ACT 250000                       // (T_LEN-1+CHUNK-1)/CHUNK
#define L_LAST    (LANES_ACT - 1)
#define NBLK      977                          // ceil(LANES_ACT/256)
#define PAD       (NBLK * BLOCK1)              // 250112
#define NGRP      500000                       // 4-row groups covering t in [1, 2000001)
#define NT0       ((NGRP + 255) / 256)         // 1954
#define K2_ITEMS  4

#define LN2_D   0.6931471805599453

// Per-lane-contiguous staging: F_c[g*CHUNK + s] = feats[(1 + g*CHUNK + s)*5 + c]
__device__ float g_F0[CHUNK * PAD];
__device__ float g_F1[CHUNK * PAD];
__device__ float g_F2[CHUNK * PAD];

__device__ float  g_Pinc[9 * PAD];    // block-local inclusive matrix prefix (SoA)
__device__ int    g_pbinc[PAD];
__device__ float  g_goldT[NT0];
__device__ float  g_Mblk[NBLK][9];
__device__ int    g_Bblk[NBLK];
__device__ float  g_Ebf[NBLK][9];     // block-exclusive prefix (fp32 + base)
__device__ int    g_EbB[NBLK];
__device__ float  g_u0f[3];
__device__ double g_c0d;
__device__ double g_partB[NBLK];
__device__ float  g_stop3[3];
__device__ unsigned g_tick1, g_tick2;

__device__ __forceinline__ void renorm9(float* P, int& base) {
    float m = fmaxf(fmaxf(fmaxf(P[0], P[1]), fmaxf(P[2], P[3])),
                    fmaxf(fmaxf(P[4], P[5]), fmaxf(P[6], fmaxf(P[7], P[8]))));
    int e = (int)(__float_as_uint(m) >> 23) - 127;
    float sc = __uint_as_float((unsigned)(127 - e) << 23);
#pragma unroll
    for (int i = 0; i < 9; ++i) P[i] *= sc;
    base += e;
}

__device__ __forceinline__ void mm9(const float* Bm, const float* A, float* C) {
#pragma unroll
    for (int i = 0; i < 3; ++i)
#pragma unroll
        for (int j = 0; j < 3; ++j)
            C[i*3+j] = Bm[i*3+0]*A[0+j] + Bm[i*3+1]*A[3+j] + Bm[i*3+2]*A[6+j];
}

// ========== K0: vectorized stage (coalesced both sides) + fused gold ==========
__global__ void __launch_bounds__(256) k_stage0(
        const float* __restrict__ feats, const int* __restrict__ tags,
        const float* __restrict__ trans) {
    __shared__ float sTr[25];
    __shared__ float sG[256];
    int tid = threadIdx.x;
    if (tid < 25) sTr[tid] = trans[tid];
    __syncthreads();

    int G = blockIdx.x * 256 + tid;
    float gold = 0.f;
    if (G < NGRP) {
        // rows t..t+3, t = 4G+1; flat float span [20G+5, 20G+24] -> 6 aligned f4 at q=5G+1
        const float4* fp = (const float4*)feats;
        int q = 5 * G + 1;
        float4 v0, v1, v2, v3, v4, v5;
        if (G < NGRP - 1) {
            v0 = fp[q];     v1 = fp[q + 1]; v2 = fp[q + 2];
            v3 = fp[q + 3]; v4 = fp[q + 4]; v5 = fp[q + 5];
        } else {            // last group: row t+3 out of range; q+4.. OOB
            v0 = fp[q];     v1 = fp[q + 1]; v2 = fp[q + 2]; v3 = fp[q + 3];
            v4 = make_float4(0.f, 0.f, 0.f, 0.f);
            v5 = make_float4(0.f, 0.f, 0.f, 0.f);
        }
        (void)v5;
        // row r comp c = flat offset o = 5r+1+c from base
        // r0: v0.y v0.z v0.w | r1: v1.z v1.w v2.x | r2: v2.w v3.x v3.y | r3: v4.x v4.y v4.z
        float4 w0 = make_float4(v0.y, v1.z, v2.w, v4.x);
        float4 w1 = make_float4(v0.z, v1.w, v3.x, v4.y);
        float4 w2 = make_float4(v0.w, v2.x, v3.y, v4.z);
        ((float4*)g_F0)[G] = w0;
        ((float4*)g_F1)[G] = w1;
        ((float4*)g_F2)[G] = w2;

        const int4* tp = (const int4*)tags;
        int4 tg = tp[G];                              // tags[4G .. 4G+3] = t-1 .. t+2
        bool r3v = (4 * G + 4 < T_LEN);
        int tg4 = r3v ? __ldg(&tags[4 * G + 4]) : 0;  // t+3

        int prev = tg.x, cur;
        cur = tg.y; gold += ((cur==0)?v0.y:(cur==1)?v0.z:v0.w) + sTr[cur*5+prev]; prev = cur;
        cur = tg.z; gold += ((cur==0)?v1.z:(cur==1)?v1.w:v2.x) + sTr[cur*5+prev]; prev = cur;
        cur = tg.w; gold += ((cur==0)?v2.w:(cur==1)?v3.x:v3.y) + sTr[cur*5+prev]; prev = cur;
        if (r3v) {
            cur = tg4;  gold += ((cur==0)?v4.x:(cur==1)?v4.y:v4.z) + sTr[cur*5+prev];
        }
    }
    sG[tid] = gold;
    __syncthreads();
    for (int k = 128; k > 0; k >>= 1) {
        if (tid < k) sG[tid] += sG[tid + k];
        __syncthreads();
    }
    if (tid == 0) g_goldT[blockIdx.x] = sG[0];
}

// ========== K1: chunk matrices + warp-shuffle scan (+ folded block scan) ==========
__global__ void __launch_bounds__(BLOCK1) k_chunks(
        const float* __restrict__ feats, const float* __restrict__ trans) {
    __shared__ float sT[8][9];  __shared__ int sbT[8];
    __shared__ float sWE[8][9]; __shared__ int sbWE[8];
    __shared__ float sP[BLOCK1][9];
    __shared__ int   sB[BLOCK1];
    __shared__ bool  sLast;

    const float L2E = 1.4426950408889634f;
    int tid = threadIdx.x, lane = tid & 31, wid = tid >> 5;
    int g = blockIdx.x * BLOCK1 + tid;

    float Tl[9];
#pragma unroll
    for (int i = 0; i < 3; ++i)
#pragma unroll
        for (int k = 0; k < 3; ++k)
            Tl[i*3+k] = exp2f(L2E * __ldg(&trans[i * NTAGS + k]));

    const float4* F04 = (const float4*)g_F0;
    const float4* F14 = (const float4*)g_F1;
    const float4* F24 = (const float4*)g_F2;
    float4 x0a = F04[2*g], x0b = F04[2*g+1];
    float4 x1a = F14[2*g], x1b = F14[2*g+1];
    float4 x2a = F24[2*g], x2b = F24[2*g+1];
    float f0s[8] = {x0a.x,x0a.y,x0a.z,x0a.w, x0b.x,x0b.y,x0b.z,x0b.w};
    float f1s[8] = {x1a.x,x1a.y,x1a.z,x1a.w, x1b.x,x1b.y,x1b.z,x1b.w};
    float f2s[8] = {x2a.x,x2a.y,x2a.z,x2a.w, x2b.x,x2b.y,x2b.z,x2b.w};

    int n = T_LEN - 1 - g * CHUNK; n = min(n, CHUNK);   // <=0 for pad lanes

    float P[9] = {1.f,0.f,0.f, 0.f,1.f,0.f, 0.f,0.f,1.f};
    int base = 0;
#pragma unroll
    for (int s = 0; s < CHUNK; ++s) {
        if (s < n) {
            float e0 = exp2f(L2E * f0s[s]), e1 = exp2f(L2E * f1s[s]), e2 = exp2f(L2E * f2s[s]);
            float a0 = e0*Tl[0], a1 = e0*Tl[1], a2 = e0*Tl[2];
            float b0 = e1*Tl[3], b1 = e1*Tl[4], b2 = e1*Tl[5];
            float d0 = e2*Tl[6], d1 = e2*Tl[7], d2 = e2*Tl[8];
            float q0 = a0*P[0] + a1*P[3] + a2*P[6];
            float q1 = a0*P[1] + a1*P[4] + a2*P[7];
            float q2 = a0*P[2] + a1*P[5] + a2*P[8];
            float q3 = b0*P[0] + b1*P[3] + b2*P[6];
            float q4 = b0*P[1] + b1*P[4] + b2*P[7];
            float q5 = b0*P[2] + b1*P[5] + b2*P[8];
            float q6 = d0*P[0] + d1*P[3] + d2*P[6];
            float q7 = d0*P[1] + d1*P[4] + d2*P[7];
            float q8 = d0*P[2] + d1*P[5] + d2*P[8];
            P[0]=q0;P[1]=q1;P[2]=q2;P[3]=q3;P[4]=q4;P[5]=q5;P[6]=q6;P[7]=q7;P[8]=q8;
        }
    }
    renorm9(P, base);

    // warp Kogge-Stone inclusive scan (later interval on the left)
#pragma unroll
    for (int s = 1; s < 32; s <<= 1) {
        float A[9];
#pragma unroll
        for (int i = 0; i < 9; ++i) A[i] = __shfl_up_sync(0xFFFFFFFFu, P[i], s);
        int ab = __shfl_up_sync(0xFFFFFFFFu, base, s);
        if (lane >= s) {
            float C[9];
            mm9(P, A, C);
            base += ab;
            renorm9(C, base);
#pragma unroll
            for (int i = 0; i < 9; ++i) P[i] = C[i];
        }
    }
    if (lane == 31) {
#pragma unroll
        for (int i = 0; i < 9; ++i) sT[wid][i] = P[i];
        sbT[wid] = base;
    }
    __syncthreads();
    if (tid < 8) {
        float E[9] = {1.f,0.f,0.f, 0.f,1.f,0.f, 0.f,0.f,1.f};
        int be = 0;
        for (int k = 0; k < tid; ++k) {
            float Tk[9], C[9];
#pragma unroll
            for (int i = 0; i < 9; ++i) Tk[i] = sT[k][i];
            mm9(Tk, E, C);
            be += sbT[k];
            renorm9(C, be);
#pragma unroll
            for (int i = 0; i < 9; ++i) E[i] = C[i];
        }
#pragma unroll
        for (int i = 0; i < 9; ++i) sWE[tid][i] = E[i];
        sbWE[tid] = be;
    }
    __syncthreads();
    {
        float WE[9], C[9];
#pragma unroll
        for (int i = 0; i < 9; ++i) WE[i] = sWE[wid][i];
        mm9(P, WE, C);
        int bb = base + sbWE[wid];
        renorm9(C, bb);
#pragma unroll
        for (int i = 0; i < 9; ++i) g_Pinc[i * PAD + g] = C[i];
        g_pbinc[g] = bb;
        if (tid == BLOCK1 - 1) {
#pragma unroll
            for (int i = 0; i < 9; ++i) g_Mblk[blockIdx.x][i] = C[i];
            g_Bblk[blockIdx.x] = bb;
        }
    }

    // -------- last-block ticket: block-exclusive scan over Mblk --------
    if (tid == 0) {
        __threadfence();
        unsigned v = atomicAdd(&g_tick1, 1u);
        sLast = (v == (unsigned)(NBLK - 1));
    }
    __syncthreads();
    if (!sLast) return;

    {
        float tot[9] = {1.f,0.f,0.f, 0.f,1.f,0.f, 0.f,0.f,1.f};
        int bt = 0;
#pragma unroll
        for (int k = 0; k < K2_ITEMS; ++k) {
            int i = tid * K2_ITEMS + k;
            if (i < NBLK) {
                float M[9], C[9];
#pragma unroll
                for (int j = 0; j < 9; ++j) M[j] = g_Mblk[i][j];
                mm9(M, tot, C);
                bt += g_Bblk[i];
                renorm9(C, bt);
#pragma unroll
                for (int j = 0; j < 9; ++j) tot[j] = C[j];
            }
        }
#pragma unroll
        for (int j = 0; j < 9; ++j) sP[tid][j] = tot[j];
        sB[tid] = bt;
    }
    __syncthreads();
    for (int s = 1; s < BLOCK1; s <<= 1) {
        float A[9], C[9]; int nb = 0; bool act = (tid >= s);
        if (act) {
            float Bm[9];
#pragma unroll
            for (int j = 0; j < 9; ++j) { Bm[j] = sP[tid][j]; A[j] = sP[tid - s][j]; }
            nb = sB[tid] + sB[tid - s];
            mm9(Bm, A, C);
            renorm9(C, nb);
        }
        __syncthreads();
        if (act) {
#pragma unroll
            for (int j = 0; j < 9; ++j) sP[tid][j] = C[j];
            sB[tid] = nb;
        }
        __syncthreads();
    }
    {
        float E[9]; int be;
        if (tid == 0) {
#pragma unroll
            for (int j = 0; j < 9; ++j) E[j] = (j % 4 == 0) ? 1.f : 0.f;
            be = 0;
        } else {
#pragma unroll
            for (int j = 0; j < 9; ++j) E[j] = sP[tid - 1][j];
            be = sB[tid - 1];
        }
#pragma unroll
        for (int k = 0; k < K2_ITEMS; ++k) {
            int i = tid * K2_ITEMS + k;
            if (i < NBLK) {
#pragma unroll
                for (int j = 0; j < 9; ++j) g_Ebf[i][j] = E[j];
                g_EbB[i] = be;
                float M[9], C[9];
#pragma unroll
                for (int j = 0; j < 9; ++j) M[j] = g_Mblk[i][j];
                mm9(M, E, C);
                be += g_Bblk[i];
                renorm9(C, be);
#pragma unroll
                for (int j = 0; j < 9; ++j) E[j] = C[j];
            }
        }
    }
    if (tid == 0) {
        double v0[3];
        for (int i = 0; i < 3; ++i) {
            double a[5]; double m = -1e300;
            for (int j = 0; j < 5; ++j) {
                a[j] = (double)trans[i * NTAGS + j] + ((j == START_T) ? 0.0 : -10000.0);
                if (a[j] > m) m = a[j];
            }
            double ss = 0.0;
            for (int j = 0; j < 5; ++j) ss += exp(a[j] - m);
            v0[i] = m + log(ss) + (double)feats[i];
        }
        double c0 = fmax(fmax(v0[0], v0[1]), v0[2]);
        g_c0d = c0;
        for (int j = 0; j < 3; ++j) g_u0f[j] = (float)exp(v0[j] - c0);
        g_tick1 = 0;
    }
}

// ========== K2: boundary (shfl-shared) + emulation (+ folded epilogue) ==========
__global__ void __launch_bounds__(BLOCK1) k_emulate(
        const float* __restrict__ feats, const int* __restrict__ tags,
        const float* __restrict__ trans, float* __restrict__ out) {
    __shared__ float  sTr[25];
    __shared__ double sPart[BLOCK1];
    __shared__ bool   sLast;
    int tid = threadIdx.x, lane = tid & 31;
    if (tid < 25) sTr[tid] = trans[tid];
    __syncthreads();

    int b = blockIdx.x;
    int g = b * BLOCK1 + tid;

    float Eb[9]; int bE = g_EbB[b];
#pragma unroll
    for (int i = 0; i < 9; ++i) Eb[i] = g_Ebf[b][i];
    float u0[3] = {g_u0f[0], g_u0f[1], g_u0f[2]};
    double c0d = g_c0d;

    // inclusive boundary Bn for this lane
    float Pg[9]; int bI = g_pbinc[g];
#pragma unroll
    for (int i = 0; i < 9; ++i) Pg[i] = g_Pinc[i * PAD + g];
    float M[9]; int bM = bI + bE;
    mm9(Pg, Eb, M);
    renorm9(M, bM);
    double tB = (double)bM * LN2_D + c0d;
    float Bn0 = (float)((double)__logf(M[0]*u0[0] + M[1]*u0[1] + M[2]*u0[2]) + tB);
    float Bn1 = (float)((double)__logf(M[3]*u0[0] + M[4]*u0[1] + M[5]*u0[2]) + tB);
    float Bn2 = (float)((double)__logf(M[6]*u0[0] + M[7]*u0[1] + M[8]*u0[2]) + tB);

    // start vector A = previous lane's Bn
    float A0 = __shfl_up_sync(0xFFFFFFFFu, Bn0, 1);
    float A1 = __shfl_up_sync(0xFFFFFFFFu, Bn1, 1);
    float A2 = __shfl_up_sync(0xFFFFFFFFu, Bn2, 1);
    if (lane == 0) {
        if (tid == 0) {             // block-first lane: exclusive prefix = Ebf
            double tE = (double)bE * LN2_D + c0d;
            A0 = (float)((double)__logf(Eb[0]*u0[0] + Eb[1]*u0[1] + Eb[2]*u0[2]) + tE);
            A1 = (float)((double)__logf(Eb[3]*u0[0] + Eb[4]*u0[1] + Eb[5]*u0[2]) + tE);
            A2 = (float)((double)__logf(Eb[6]*u0[0] + Eb[7]*u0[1] + Eb[8]*u0[2]) + tE);
        } else {                    // warp-first lane: from Pinc[g-1]
            float Pm[9]; int bm = g_pbinc[g - 1];
#pragma unroll
            for (int i = 0; i < 9; ++i) Pm[i] = g_Pinc[i * PAD + (g - 1)];
            float Mm[9]; int b2 = bm + bE;
            mm9(Pm, Eb, Mm);
            renorm9(Mm, b2);
            double t2 = (double)b2 * LN2_D + c0d;
            A0 = (float)((double)__logf(Mm[0]*u0[0] + Mm[1]*u0[1] + Mm[2]*u0[2]) + t2);
            A1 = (float)((double)__logf(Mm[3]*u0[0] + Mm[4]*u0[1] + Mm[5]*u0[2]) + t2);
            A2 = (float)((double)__logf(Mm[6]*u0[0] + Mm[7]*u0[1] + Mm[8]*u0[2]) + t2);
        }
    }

    // fp32 absolute-scale quantized walk
    const float4* F04 = (const float4*)g_F0;
    const float4* F14 = (const float4*)g_F1;
    const float4* F24 = (const float4*)g_F2;
    float4 x0a = F04[2*g], x0b = F04[2*g+1];
    float4 x1a = F14[2*g], x1b = F14[2*g+1];
    float4 x2a = F24[2*g], x2b = F24[2*g+1];
    float f0s[8] = {x0a.x,x0a.y,x0a.z,x0a.w, x0b.x,x0b.y,x0b.z,x0b.w};
    float f1s[8] = {x1a.x,x1a.y,x1a.z,x1a.w, x1b.x,x1b.y,x1b.z,x1b.w};
    float f2s[8] = {x2a.x,x2a.y,x2a.z,x2a.w, x2b.x,x2b.y,x2b.z,x2b.w};

    float t00 = sTr[0],  t01 = sTr[1],  t02 = sTr[2];
    float t10 = sTr[5],  t11 = sTr[6],  t12 = sTr[7];
    float t20 = sTr[10], t21 = sTr[11], t22 = sTr[12];

    float fv0 = A0, fv1 = A1, fv2 = A2;
    int n = T_LEN - 1 - g * CHUNK; n = min(n, CHUNK);

#pragma unroll
    for (int s = 0; s < CHUNK; ++s) {
        if (s < n) {
            float f0 = f0s[s], f1 = f1s[s], f2 = f2s[s];
            float a00=__fadd_rn(fv0,t00), a01=__fadd_rn(fv1,t01), a02=__fadd_rn(fv2,t02);
            float a10=__fadd_rn(fv0,t10), a11=__fadd_rn(fv1,t11), a12=__fadd_rn(fv2,t12);
            float a20=__fadd_rn(fv0,t20), a21=__fadd_rn(fv1,t21), a22=__fadd_rn(fv2,t22);
            float m0=fmaxf(fmaxf(a00,a01),a02);
            float m1=fmaxf(fmaxf(a10,a11),a12);
            float m2=fmaxf(fmaxf(a20,a21),a22);
            float s0=__expf(a00-m0)+__expf(a01-m0)+__expf(a02-m0);
            float s1=__expf(a10-m1)+__expf(a11-m1)+__expf(a12-m1);
            float s2=__expf(a20-m2)+__expf(a21-m2)+__expf(a22-m2);
            fv0=__fadd_rn(__fadd_rn(__logf(s0),m0),f0);
            fv1=__fadd_rn(__fadd_rn(__logf(s1),m1),f1);
            fv2=__fadd_rn(__fadd_rn(__logf(s2),m2),f2);
        }
    }

    double part = 0.0;
    if (g < L_LAST) {
        part = (((double)fv0 - (double)Bn0)
              + ((double)fv1 - (double)Bn1)
              + ((double)fv2 - (double)Bn2)) / 3.0;
    } else if (g == L_LAST) {
        g_stop3[0] = __fadd_rn(fv0, sTr[STOP_T * NTAGS + 0]);
        g_stop3[1] = __fadd_rn(fv1, sTr[STOP_T * NTAGS + 1]);
        g_stop3[2] = __fadd_rn(fv2, sTr[STOP_T * NTAGS + 2]);
    }

    sPart[tid] = part;
    __syncthreads();
    for (int k = BLOCK1 / 2; k > 0; k >>= 1) {
        if (tid < k) sPart[tid] += sPart[tid + k];
        __syncthreads();
    }
    if (tid == 0) g_partB[blockIdx.x] = sPart[0];

    // -------- last-block ticket: final reductions + epilogue --------
    if (tid == 0) {
        __threadfence();
        unsigned v = atomicAdd(&g_tick2, 1u);
        sLast = (v == (unsigned)(NBLK - 1));
    }
    __syncthreads();
    if (!sLast) return;

    double s = 0.0;
    for (int i = tid; i < NBLK; i += BLOCK1) s += g_partB[i];
    sPart[tid] = s; __syncthreads();
    for (int k = BLOCK1 / 2; k > 0; k >>= 1) {
        if (tid < k) sPart[tid] += sPart[tid + k];
        __syncthreads();
    }
    double mu = sPart[0]; __syncthreads();

    double sg = 0.0;
    for (int i = tid; i < NT0; i += BLOCK1) sg += (double)g_goldT[i];
    sPart[tid] = sg; __syncthreads();
    for (int k = BLOCK1 / 2; k > 0; k >>= 1) {
        if (tid < k) sPart[tid] += sPart[tid + k];
        __syncthreads();
    }
    double goldsum = sPart[0];

    if (tid == 0) {
        double b0 = (double)g_stop3[0], b1 = (double)g_stop3[1], b2 = (double)g_stop3[2];
        double m = fmax(fmax(b0, b1), b2);
        double alpha = m + log(exp(b0 - m) + exp(b1 - m) + exp(b2 - m)) + mu;

        int tg0 = tags[0];
        int tgL = tags[T_LEN - 1];
        double gold = goldsum
                    + (double)trans[tg0 * NTAGS + START_T]
                    + (double)feats[tg0]
                    + (double)trans[STOP_T * NTAGS + tgL];
        out[0] = (float)(alpha - gold);
        g_tick2 = 0;
    }
}

extern "C" void kernel_launch(void* const* d_in, const int* in_sizes, int n_in,
                              void* d_out, int out_size) {
    const float* feats = nullptr;
    const int*   tags  = nullptr;
    const float* trans = nullptr;
    for (int i = 0; i < n_in; ++i) {
        if (in_sizes[i] == NTAGS * NTAGS)      trans = (const float*)d_in[i];
        else if (in_sizes[i] == T_LEN)         tags  = (const int*)d_in[i];
        else                                   feats = (const float*)d_in[i];
    }
    float* out = (float*)d_out;

    k_stage0<<<NT0, 256>>>(feats, tags, trans);
    k_chunks<<<NBLK, BLOCK1>>>(feats, trans);
    k_emulate<<<NBLK, BLOCK1>>>(feats, tags, trans, out);
}